// round 15
// baseline (speedup 1.0000x reference)
#include <cuda_runtime.h>
#include <cuda_fp16.h>
#include <cstdint>

// ---------------- Problem constants ----------------
#define BQ 256
#define AQ 128
#define FQ 512      // GEMM K
#define DQ 6
#define CQ 512      // GEMM N total
#define BA (BQ*AQ)               // 32768 atoms

// ---------------- GEMM tiling ----------------
#define MT 128
#define NT 128
#define KC 64                  // k-tile: 64 fp16 = 128B rows (8x16B chunks, XOR-swizzled)
#define NK (FQ/KC)             // 8
#define OFF_A 0
#define OFF_B 16384
#define STAGE_B 32768
#define DYN_SMEM (2*STAGE_B + 1024)
#define MAXTILES (BA/MT + DQ)  // 262: upper bound on populated M-tiles

// ---------------- mid-kernel block layout (gather FIRST) ----------------
#define GATHER_BLOCKS (BA / 8)                 // 4096 (warp-per-atom gather)
#define WT_BLOCKS (DQ * (FQ / 32) * (CQ / 32)) // 1536 (W transpose)
#define BKT_BLOCKS (BA / 256)                  // 128  (bucket lists)
#define MID_BLOCKS (GATHER_BLOCKS + WT_BLOCKS + BKT_BLOCKS)

// ---------------- Static scratch (no runtime allocation) ----------------
__device__ __half g_Ah[(size_t)BA * FQ];       // summed atom features (natural order)
__device__ __half g_Wh[(size_t)DQ * CQ * FQ];  // weights [d][n][k] transposed, fp16
__device__ int g_lists[DQ][BA];                // per-degree atom id lists
__device__ int g_counts[DQ];                   // transient (reset by scan block)
__device__ int g_cnt2[DQ];                     // published per-degree counts
__device__ int g_tilemap[MAXTILES];            // (d << 16) | m-tile-within-bucket
__device__ int g_ntiles;
__device__ int g_ticket;                       // self-resetting block ticket

// ---------------- helpers ----------------
static __device__ __forceinline__ uint32_t smem_u32(const void* p) {
    uint32_t a;
    asm("{ .reg .u64 t; cvta.to.shared.u64 t, %1; cvt.u32.u64 %0, t; }"
        : "=r"(a) : "l"(p));
    return a;
}
static __device__ __forceinline__ void cp16(uint32_t dst, const void* src) {
    asm volatile("cp.async.cg.shared.global [%0], [%1], 16;"
                 :: "r"(dst), "l"(src) : "memory");
}
#define LDSM_X4(r, addr) \
    asm volatile("ldmatrix.sync.aligned.m8n8.x4.shared.b16 {%0,%1,%2,%3}, [%4];" \
                 : "=r"((r)[0]), "=r"((r)[1]), "=r"((r)[2]), "=r"((r)[3]) \
                 : "r"(addr))
static __device__ __forceinline__ void mma_fp16(float* c, const uint32_t* a,
                                                const uint32_t* b) {
    asm volatile(
        "mma.sync.aligned.m16n8k16.row.col.f32.f16.f16.f32 "
        "{%0,%1,%2,%3}, {%4,%5,%6,%7}, {%8,%9}, {%0,%1,%2,%3};"
        : "+f"(c[0]), "+f"(c[1]), "+f"(c[2]), "+f"(c[3])
        : "r"(a[0]), "r"(a[1]), "r"(a[2]), "r"(a[3]), "r"(b[0]), "r"(b[1]));
}
// SW128-style XOR swizzle: offset(row, 16B-chunk j) within a 128B-row tile
static __device__ __forceinline__ uint32_t swz(int row, int j) {
    return (uint32_t)(row * 128 + ((j ^ (row & 7)) * 16));
}

// ---------------------------------------------------------------------------
// Kernel A (single mid kernel, three independent block families):
//   [0, 4096):     warp-per-atom gather+sum -> fp16 at NATURAL atom row
//                  (DRAM-heavy; scheduled first so HBM saturates immediately)
//   [4096, 5632):  W [d][k][n] -> [d][n][k] fp16 transpose
//   [5632, 5760):  per-degree list build; LAST of these publishes
//                  cnt2/tilemap/ntiles + self-resets.
// The GEMM kernel boundary synchronizes everything.
// ---------------------------------------------------------------------------
__global__ __launch_bounds__(256) void mid_kernel(
    const float* __restrict__ atoms, const int* __restrict__ bonds,
    const float* __restrict__ W)
{
    const int bid = blockIdx.x;

    if (bid < GATHER_BLOCKS) {
        // ---------------- gather: one warp per atom, natural row ----------
        const int wid  = bid * 8 + (threadIdx.x >> 5);
        const int lane = threadIdx.x & 31;
        const int mol  = wid >> 7;

        int nbv = -1;
        if (lane < DQ) nbv = bonds[(size_t)wid * DQ + lane];

        const float4* A4 = reinterpret_cast<const float4*>(atoms);
        const float4* base = A4 + (size_t)mol * AQ * (FQ / 4);
        const float4* self = A4 + (size_t)wid * (FQ / 4);

        float4 acc[4];
        #pragma unroll
        for (int q = 0; q < 4; q++) acc[q] = self[lane + 32 * q];

        #pragma unroll
        for (int i = 0; i < DQ; i++) {
            int nb = __shfl_sync(0xFFFFFFFFu, nbv, i);
            if (nb >= 0) {
                const float4* np = base + (size_t)nb * (FQ / 4);
                #pragma unroll
                for (int q = 0; q < 4; q++) {
                    float4 v = np[lane + 32 * q];
                    acc[q].x += v.x; acc[q].y += v.y; acc[q].z += v.z; acc[q].w += v.w;
                }
            }
        }

        #pragma unroll
        for (int q = 0; q < 4; q++) {
            __half2 h01 = __floats2half2_rn(acc[q].x, acc[q].y);
            __half2 h23 = __floats2half2_rn(acc[q].z, acc[q].w);
            uint2 pk;
            pk.x = *reinterpret_cast<uint32_t*>(&h01);
            pk.y = *reinterpret_cast<uint32_t*>(&h23);
            size_t o = (size_t)wid * FQ + (lane + 32 * q) * 4;
            *reinterpret_cast<uint2*>(g_Ah + o) = pk;    // one 8B store per chain
        }
    } else if (bid < GATHER_BLOCKS + WT_BLOCKS) {
        // ---------------- W transpose 32x32 tile -> fp16 [d][n][k] ---------
        __shared__ float tile[32][33];
        const int b2 = bid - GATHER_BLOCKS;               // 0..1535
        const int d   = b2 >> 8;
        const int rem = b2 & 255;
        const int kb = (rem & 15) * 32;
        const int nb = (rem >> 4) * 32;
        const int tx = threadIdx.x & 31;
        const int ty = threadIdx.x >> 5;
        #pragma unroll
        for (int i = 0; i < 4; i++)
            tile[ty + 8 * i][tx] = W[((size_t)d * FQ + kb + ty + 8 * i) * CQ + nb + tx];
        __syncthreads();
        #pragma unroll
        for (int i = 0; i < 4; i++) {
            float v = tile[tx][ty + 8 * i];
            g_Wh[((size_t)d * CQ + nb + ty + 8 * i) * FQ + kb + tx] = __float2half_rn(v);
        }
    } else {
        // ---------------- bucket list build ----------------
        const int tid = threadIdx.x;
        const int bbid = bid - GATHER_BLOCKS - WT_BLOCKS; // 0..127
        __shared__ int s_hist[DQ];
        __shared__ int s_basep[DQ];

        if (tid < DQ) s_hist[tid] = 0;
        __syncthreads();
        const int i = bbid * 256 + tid;
        const int* bd = bonds + (size_t)i * DQ;
        int deg = 0;
        #pragma unroll
        for (int k = 0; k < DQ; k++) deg += (bd[k] >= 0);
        if (deg > DQ - 1) deg = DQ - 1;
        int rank = atomicAdd(&s_hist[deg], 1);
        __syncthreads();
        if (tid < DQ)
            s_basep[tid] = atomicAdd(&g_counts[tid], s_hist[tid]);
        __syncthreads();
        g_lists[deg][s_basep[deg] + rank] = i;

        __syncthreads();
        if (tid == 0) {
            __threadfence();
            int t = atomicAdd(&g_ticket, 1);
            if (t == BKT_BLOCKS - 1) {
                int nt = 0;
                #pragma unroll
                for (int dd = 0; dd < DQ; dd++) {
                    int c = g_counts[dd];
                    g_cnt2[dd] = c;
                    int tiles = (c + MT - 1) / MT;
                    for (int tt = 0; tt < tiles; tt++)
                        g_tilemap[nt++] = (dd << 16) | tt;
                    g_counts[dd] = 0;      // ready for next graph replay
                }
                g_ntiles = nt;
                g_ticket = 0;              // self-reset
                __threadfence();
            }
        }
    }
}

// ---------------------------------------------------------------------------
// Kernel B: gathered-A fp16 GEMM via mma.sync.m16n8k16, fp32 accumulate.
// CTA 128x128, 8 warps (2x4), warp tile 64x32; BK=64, 2-stage cp.async.
// A rows indirected through the per-tile row list. Mainloop frozen
// (measured-best; R5/R7/R9 restructures all regressed).
// ---------------------------------------------------------------------------
static __device__ __forceinline__ void load_stage(uint32_t sb, const int* rowA,
                                                  int wrow, int k0, int tid) {
    #pragma unroll
    for (int i = 0; i < 4; i++) {
        int c = i * 256 + tid;          // 1024 16B-chunks per 16KB tile
        int r = c >> 3, j = c & 7;
        uint32_t off = swz(r, j);
        cp16(sb + OFF_A + off, g_Ah + (size_t)rowA[i] * FQ + k0 + j * 8);
        cp16(sb + OFF_B + off, g_Wh + (size_t)(wrow + r) * FQ + k0 + j * 8);
    }
    asm volatile("cp.async.commit_group;" ::: "memory");
}

__global__ __launch_bounds__(256, 2) void gemm_mma_kernel(
    const float* __restrict__ bias, float* __restrict__ out)
{
    if ((int)blockIdx.x >= g_ntiles) return;
    const int map = g_tilemap[blockIdx.x];
    const int d = map >> 16;
    const int tt = map & 0xFFFF;
    const int n0 = blockIdx.y * NT;
    const int wrow = d * CQ + n0;

    __shared__ int s_rows[MT];
    extern __shared__ char dsm[];
    const uint32_t sb = (smem_u32(dsm) + 1023u) & ~1023u;
    const int tid = threadIdx.x, wid = tid >> 5, lane = tid & 31;
    const int wm = (wid & 1) * 64;       // warp M offset in tile
    const int wn = (wid >> 1) * 32;      // warp N offset in tile

    if (tid < MT) {
        int s = tt * MT + tid;
        s_rows[tid] = (s < g_cnt2[d]) ? g_lists[d][s] : -1;
    }
    __syncthreads();

    // Per-thread A-load row ids (constant across all k-iterations).
    int rowA[4];
    #pragma unroll
    for (int i = 0; i < 4; i++) {
        int r = (i * 256 + tid) >> 3;
        int rr = s_rows[r];
        rowA[i] = (rr < 0) ? 0 : rr;     // clamp: garbage rows are discarded
    }
    // Epilogue row ids.
    const int g  = lane >> 2;
    const int t4 = lane & 3;
    int arow[4][2];
    #pragma unroll
    for (int i = 0; i < 4; i++) {
        arow[i][0] = s_rows[wm + i * 16 + g];
        arow[i][1] = s_rows[wm + i * 16 + g + 8];
    }

    float acc[4][4][4];
    #pragma unroll
    for (int i = 0; i < 4; i++)
        #pragma unroll
        for (int j = 0; j < 4; j++)
            #pragma unroll
            for (int q = 0; q < 4; q++) acc[i][j][q] = 0.f;

    const int a_row = wm + (lane & 15);
    const int a_jlo = lane >> 4;
    const int b_mi  = lane >> 3;
    const int b_rb  = wn + ((b_mi >> 1) * 8) + (lane & 7);
    const int b_jlo = b_mi & 1;

    load_stage(sb, rowA, wrow, 0, tid);
    load_stage(sb + STAGE_B, rowA, wrow, KC, tid);

    #pragma unroll 1
    for (int c = 0; c < NK; c++) {
        const uint32_t st = sb + (c & 1) * STAGE_B;
        if (c < NK - 1) asm volatile("cp.async.wait_group 1;" ::: "memory");
        else            asm volatile("cp.async.wait_group 0;" ::: "memory");
        __syncthreads();

        #pragma unroll
        for (int s = 0; s < 4; s++) {               // 4 x k16 per k-tile
            uint32_t ah[4][4], bh[4][2];
            #pragma unroll
            for (int i = 0; i < 4; i++) {
                int row = a_row + i * 16;
                LDSM_X4(ah[i], st + OFF_A + swz(row, s * 2 + a_jlo));
            }
            #pragma unroll
            for (int jj = 0; jj < 2; jj++) {
                int row = b_rb + jj * 16;
                uint32_t r4[4];
                LDSM_X4(r4, st + OFF_B + swz(row, s * 2 + b_jlo));
                bh[jj*2][0] = r4[0]; bh[jj*2][1] = r4[1];
                bh[jj*2+1][0] = r4[2]; bh[jj*2+1][1] = r4[3];
            }
            #pragma unroll
            for (int i = 0; i < 4; i++)
                #pragma unroll
                for (int j = 0; j < 4; j++)
                    mma_fp16(acc[i][j], ah[i], bh[j]);
        }
        __syncthreads();
        if (c + 2 < NK)
            load_stage(sb + (c & 1) * STAGE_B, rowA, wrow, (c + 2) * KC, tid);
    }

    // ---- Epilogue: scatter rows back by atom id, add bias. ----
    float2 bb[4];
    #pragma unroll
    for (int j = 0; j < 4; j++)
        bb[j] = *reinterpret_cast<const float2*>(
                    bias + d * CQ + n0 + wn + j * 8 + t4 * 2);

    #pragma unroll
    for (int i = 0; i < 4; i++) {
        const int a0 = arow[i][0];
        const int a1 = arow[i][1];
        #pragma unroll
        for (int j = 0; j < 4; j++) {
            const int col = n0 + wn + j * 8 + t4 * 2;
            if (a0 >= 0) {
                float2 v = make_float2(acc[i][j][0] + bb[j].x, acc[i][j][1] + bb[j].y);
                *reinterpret_cast<float2*>(out + (size_t)a0 * CQ + col) = v;
            }
            if (a1 >= 0) {
                float2 v = make_float2(acc[i][j][2] + bb[j].x, acc[i][j][3] + bb[j].y);
                *reinterpret_cast<float2*>(out + (size_t)a1 * CQ + col) = v;
            }
        }
    }
}

// ---------------------------------------------------------------------------
// Launch
// ---------------------------------------------------------------------------
extern "C" void kernel_launch(void* const* d_in, const int* in_sizes, int n_in,
                              void* d_out, int out_size)
{
    const float* atoms = (const float*)d_in[0];   // [B, A, F] fp32
    const int*   bonds = (const int*)  d_in[1];   // [B, A, D] int32
    const float* W     = (const float*)d_in[2];   // [D, F, C] fp32
    const float* bias  = (const float*)d_in[3];   // [D, C]    fp32
    float*       out   = (float*)d_out;           // [B, A, C] fp32

    cudaFuncSetAttribute(gemm_mma_kernel,
                         cudaFuncAttributeMaxDynamicSharedMemorySize, DYN_SMEM);

    mid_kernel<<<MID_BLOCKS, 256>>>(atoms, bonds, W);
    gemm_mma_kernel<<<dim3(MAXTILES, CQ / NT), 256, DYN_SMEM>>>(bias, out);
}

// round 16
// speedup vs baseline: 1.0267x; 1.0267x over previous
#include <cuda_runtime.h>
#include <cuda_fp16.h>
#include <cstdint>

// ---------------- Problem constants ----------------
#define BQ 256
#define AQ 128
#define FQ 512      // GEMM K
#define DQ 6
#define CQ 512      // GEMM N total
#define BA (BQ*AQ)               // 32768 atoms

// ---------------- GEMM tiling ----------------
#define MT 128
#define NT 128
#define KC 64                  // k-tile: 64 fp16 = 128B rows (8x16B chunks, XOR-swizzled)
#define NK (FQ/KC)             // 8
#define OFF_A 0
#define OFF_B 16384
#define STAGE_B 32768
#define DYN_SMEM (2*STAGE_B + 1024)
#define MAXTILES (BA/MT + DQ)  // 262: upper bound on populated M-tiles

// ---------------- mid-kernel block layout (bucket FIRST, as in R13) ------
#define BKT_BLOCKS (BA / 256)                  // 128  (bucket lists)
#define GATHER_BLOCKS (BA / 8)                 // 4096 (warp-per-atom gather)
#define WT_BLOCKS (DQ * (FQ / 32) * (CQ / 32)) // 1536 (W transpose)
#define MID_BLOCKS (BKT_BLOCKS + GATHER_BLOCKS + WT_BLOCKS)

// ---------------- Static scratch (no runtime allocation) ----------------
__device__ __half g_Ah[(size_t)BA * FQ];       // summed atom features (natural order)
__device__ __half g_Wh[(size_t)DQ * CQ * FQ];  // weights [d][n][k] transposed, fp16
__device__ int g_lists[DQ][BA];                // per-degree atom id lists
__device__ int g_counts[DQ];                   // transient (reset by scan block)
__device__ int g_cnt2[DQ];                     // published per-degree counts
__device__ int g_tilemap[MAXTILES];            // (d << 16) | m-tile-within-bucket
__device__ int g_ntiles;
__device__ int g_ticket;                       // self-resetting block ticket

// ---------------- helpers ----------------
static __device__ __forceinline__ uint32_t smem_u32(const void* p) {
    uint32_t a;
    asm("{ .reg .u64 t; cvta.to.shared.u64 t, %1; cvt.u32.u64 %0, t; }"
        : "=r"(a) : "l"(p));
    return a;
}
static __device__ __forceinline__ void cp16(uint32_t dst, const void* src) {
    asm volatile("cp.async.cg.shared.global [%0], [%1], 16;"
                 :: "r"(dst), "l"(src) : "memory");
}
#define LDSM_X4(r, addr) \
    asm volatile("ldmatrix.sync.aligned.m8n8.x4.shared.b16 {%0,%1,%2,%3}, [%4];" \
                 : "=r"((r)[0]), "=r"((r)[1]), "=r"((r)[2]), "=r"((r)[3]) \
                 : "r"(addr))
static __device__ __forceinline__ void mma_fp16(float* c, const uint32_t* a,
                                                const uint32_t* b) {
    asm volatile(
        "mma.sync.aligned.m16n8k16.row.col.f32.f16.f16.f32 "
        "{%0,%1,%2,%3}, {%4,%5,%6,%7}, {%8,%9}, {%0,%1,%2,%3};"
        : "+f"(c[0]), "+f"(c[1]), "+f"(c[2]), "+f"(c[3])
        : "r"(a[0]), "r"(a[1]), "r"(a[2]), "r"(a[3]), "r"(b[0]), "r"(b[1]));
}
// SW128-style XOR swizzle: offset(row, 16B-chunk j) within a 128B-row tile
static __device__ __forceinline__ uint32_t swz(int row, int j) {
    return (uint32_t)(row * 128 + ((j ^ (row & 7)) * 16));
}

// ---------------------------------------------------------------------------
// Kernel A (single mid kernel, three independent block families):
//   [0, 128):      per-degree list build; LAST of these publishes
//                  cnt2/tilemap/ntiles + self-resets. Scheduled FIRST so
//                  the scan completes early and hides under gather.
//   [128, 4224):   warp-per-atom gather+sum -> fp16 at NATURAL atom row.
//   [4224, 5760):  W [d][k][n] -> [d][n][k] fp16 transpose.
// The GEMM kernel boundary synchronizes everything.
// ---------------------------------------------------------------------------
__global__ __launch_bounds__(256) void mid_kernel(
    const float* __restrict__ atoms, const int* __restrict__ bonds,
    const float* __restrict__ W)
{
    const int bid = blockIdx.x;

    if (bid < BKT_BLOCKS) {
        // ---------------- bucket list build ----------------
        const int tid = threadIdx.x;
        __shared__ int s_hist[DQ];
        __shared__ int s_basep[DQ];

        if (tid < DQ) s_hist[tid] = 0;
        __syncthreads();
        const int i = bid * 256 + tid;
        const int* bd = bonds + (size_t)i * DQ;
        int deg = 0;
        #pragma unroll
        for (int k = 0; k < DQ; k++) deg += (bd[k] >= 0);
        if (deg > DQ - 1) deg = DQ - 1;
        int rank = atomicAdd(&s_hist[deg], 1);
        __syncthreads();
        if (tid < DQ)
            s_basep[tid] = atomicAdd(&g_counts[tid], s_hist[tid]);
        __syncthreads();
        g_lists[deg][s_basep[deg] + rank] = i;

        __syncthreads();
        if (tid == 0) {
            __threadfence();
            int t = atomicAdd(&g_ticket, 1);
            if (t == BKT_BLOCKS - 1) {
                int nt = 0;
                #pragma unroll
                for (int dd = 0; dd < DQ; dd++) {
                    int c = g_counts[dd];
                    g_cnt2[dd] = c;
                    int tiles = (c + MT - 1) / MT;
                    for (int tt = 0; tt < tiles; tt++)
                        g_tilemap[nt++] = (dd << 16) | tt;
                    g_counts[dd] = 0;      // ready for next graph replay
                }
                g_ntiles = nt;
                g_ticket = 0;              // self-reset
                __threadfence();
            }
        }
    } else if (bid < BKT_BLOCKS + GATHER_BLOCKS) {
        // ---------------- gather: one warp per atom, natural row ----------
        const int wid  = (bid - BKT_BLOCKS) * 8 + (threadIdx.x >> 5);
        const int lane = threadIdx.x & 31;
        const int mol  = wid >> 7;

        int nbv = -1;
        if (lane < DQ) nbv = bonds[(size_t)wid * DQ + lane];

        const float4* A4 = reinterpret_cast<const float4*>(atoms);
        const float4* base = A4 + (size_t)mol * AQ * (FQ / 4);
        const float4* self = A4 + (size_t)wid * (FQ / 4);

        float4 acc[4];
        #pragma unroll
        for (int q = 0; q < 4; q++) acc[q] = self[lane + 32 * q];

        #pragma unroll
        for (int i = 0; i < DQ; i++) {
            int nb = __shfl_sync(0xFFFFFFFFu, nbv, i);
            if (nb >= 0) {
                const float4* np = base + (size_t)nb * (FQ / 4);
                #pragma unroll
                for (int q = 0; q < 4; q++) {
                    float4 v = np[lane + 32 * q];
                    acc[q].x += v.x; acc[q].y += v.y; acc[q].z += v.z; acc[q].w += v.w;
                }
            }
        }

        #pragma unroll
        for (int q = 0; q < 4; q++) {
            __half2 h01 = __floats2half2_rn(acc[q].x, acc[q].y);
            __half2 h23 = __floats2half2_rn(acc[q].z, acc[q].w);
            uint2 pk;
            pk.x = *reinterpret_cast<uint32_t*>(&h01);
            pk.y = *reinterpret_cast<uint32_t*>(&h23);
            size_t o = (size_t)wid * FQ + (lane + 32 * q) * 4;
            *reinterpret_cast<uint2*>(g_Ah + o) = pk;    // one 8B store per chain
        }
    } else {
        // ---------------- W transpose 32x32 tile -> fp16 [d][n][k] ---------
        __shared__ float tile[32][33];
        const int b2 = bid - BKT_BLOCKS - GATHER_BLOCKS;  // 0..1535
        const int d   = b2 >> 8;
        const int rem = b2 & 255;
        const int kb = (rem & 15) * 32;
        const int nb = (rem >> 4) * 32;
        const int tx = threadIdx.x & 31;
        const int ty = threadIdx.x >> 5;
        #pragma unroll
        for (int i = 0; i < 4; i++)
            tile[ty + 8 * i][tx] = W[((size_t)d * FQ + kb + ty + 8 * i) * CQ + nb + tx];
        __syncthreads();
        #pragma unroll
        for (int i = 0; i < 4; i++) {
            float v = tile[tx][ty + 8 * i];
            g_Wh[((size_t)d * CQ + nb + ty + 8 * i) * FQ + kb + tx] = __float2half_rn(v);
        }
    }
}

// ---------------------------------------------------------------------------
// Kernel B: gathered-A fp16 GEMM via mma.sync.m16n8k16, fp32 accumulate.
// CTA 128x128, 8 warps (2x4), warp tile 64x32; BK=64, 2-stage cp.async.
// A rows indirected through the per-tile row list. Mainloop frozen
// (measured-best; R5/R7/R9 restructures all regressed).
// ---------------------------------------------------------------------------
static __device__ __forceinline__ void load_stage(uint32_t sb, const int* rowA,
                                                  int wrow, int k0, int tid) {
    #pragma unroll
    for (int i = 0; i < 4; i++) {
        int c = i * 256 + tid;          // 1024 16B-chunks per 16KB tile
        int r = c >> 3, j = c & 7;
        uint32_t off = swz(r, j);
        cp16(sb + OFF_A + off, g_Ah + (size_t)rowA[i] * FQ + k0 + j * 8);
        cp16(sb + OFF_B + off, g_Wh + (size_t)(wrow + r) * FQ + k0 + j * 8);
    }
    asm volatile("cp.async.commit_group;" ::: "memory");
}

__global__ __launch_bounds__(256, 2) void gemm_mma_kernel(
    const float* __restrict__ bias, float* __restrict__ out)
{
    if ((int)blockIdx.x >= g_ntiles) return;
    const int map = g_tilemap[blockIdx.x];
    const int d = map >> 16;
    const int tt = map & 0xFFFF;
    const int n0 = blockIdx.y * NT;
    const int wrow = d * CQ + n0;

    __shared__ int s_rows[MT];
    extern __shared__ char dsm[];
    const uint32_t sb = (smem_u32(dsm) + 1023u) & ~1023u;
    const int tid = threadIdx.x, wid = tid >> 5, lane = tid & 31;
    const int wm = (wid & 1) * 64;       // warp M offset in tile
    const int wn = (wid >> 1) * 32;      // warp N offset in tile

    if (tid < MT) {
        int s = tt * MT + tid;
        s_rows[tid] = (s < g_cnt2[d]) ? g_lists[d][s] : -1;
    }
    __syncthreads();

    // Per-thread A-load row ids (constant across all k-iterations).
    int rowA[4];
    #pragma unroll
    for (int i = 0; i < 4; i++) {
        int r = (i * 256 + tid) >> 3;
        int rr = s_rows[r];
        rowA[i] = (rr < 0) ? 0 : rr;     // clamp: garbage rows are discarded
    }
    // Epilogue row ids.
    const int g  = lane >> 2;
    const int t4 = lane & 3;
    int arow[4][2];
    #pragma unroll
    for (int i = 0; i < 4; i++) {
        arow[i][0] = s_rows[wm + i * 16 + g];
        arow[i][1] = s_rows[wm + i * 16 + g + 8];
    }

    float acc[4][4][4];
    #pragma unroll
    for (int i = 0; i < 4; i++)
        #pragma unroll
        for (int j = 0; j < 4; j++)
            #pragma unroll
            for (int q = 0; q < 4; q++) acc[i][j][q] = 0.f;

    const int a_row = wm + (lane & 15);
    const int a_jlo = lane >> 4;
    const int b_mi  = lane >> 3;
    const int b_rb  = wn + ((b_mi >> 1) * 8) + (lane & 7);
    const int b_jlo = b_mi & 1;

    load_stage(sb, rowA, wrow, 0, tid);
    load_stage(sb + STAGE_B, rowA, wrow, KC, tid);

    #pragma unroll 1
    for (int c = 0; c < NK; c++) {
        const uint32_t st = sb + (c & 1) * STAGE_B;
        if (c < NK - 1) asm volatile("cp.async.wait_group 1;" ::: "memory");
        else            asm volatile("cp.async.wait_group 0;" ::: "memory");
        __syncthreads();

        #pragma unroll
        for (int s = 0; s < 4; s++) {               // 4 x k16 per k-tile
            uint32_t ah[4][4], bh[4][2];
            #pragma unroll
            for (int i = 0; i < 4; i++) {
                int row = a_row + i * 16;
                LDSM_X4(ah[i], st + OFF_A + swz(row, s * 2 + a_jlo));
            }
            #pragma unroll
            for (int jj = 0; jj < 2; jj++) {
                int row = b_rb + jj * 16;
                uint32_t r4[4];
                LDSM_X4(r4, st + OFF_B + swz(row, s * 2 + b_jlo));
                bh[jj*2][0] = r4[0]; bh[jj*2][1] = r4[1];
                bh[jj*2+1][0] = r4[2]; bh[jj*2+1][1] = r4[3];
            }
            #pragma unroll
            for (int i = 0; i < 4; i++)
                #pragma unroll
                for (int j = 0; j < 4; j++)
                    mma_fp16(acc[i][j], ah[i], bh[j]);
        }
        __syncthreads();
        if (c + 2 < NK)
            load_stage(sb + (c & 1) * STAGE_B, rowA, wrow, (c + 2) * KC, tid);
    }

    // ---- Epilogue: scatter rows back by atom id, add bias. ----
    float2 bb[4];
    #pragma unroll
    for (int j = 0; j < 4; j++)
        bb[j] = *reinterpret_cast<const float2*>(
                    bias + d * CQ + n0 + wn + j * 8 + t4 * 2);

    #pragma unroll
    for (int i = 0; i < 4; i++) {
        const int a0 = arow[i][0];
        const int a1 = arow[i][1];
        #pragma unroll
        for (int j = 0; j < 4; j++) {
            const int col = n0 + wn + j * 8 + t4 * 2;
            if (a0 >= 0) {
                float2 v = make_float2(acc[i][j][0] + bb[j].x, acc[i][j][1] + bb[j].y);
                *reinterpret_cast<float2*>(out + (size_t)a0 * CQ + col) = v;
            }
            if (a1 >= 0) {
                float2 v = make_float2(acc[i][j][2] + bb[j].x, acc[i][j][3] + bb[j].y);
                *reinterpret_cast<float2*>(out + (size_t)a1 * CQ + col) = v;
            }
        }
    }
}

// ---------------------------------------------------------------------------
// Launch
// ---------------------------------------------------------------------------
extern "C" void kernel_launch(void* const* d_in, const int* in_sizes, int n_in,
                              void* d_out, int out_size)
{
    const float* atoms = (const float*)d_in[0];   // [B, A, F] fp32
    const int*   bonds = (const int*)  d_in[1];   // [B, A, D] int32
    const float* W     = (const float*)d_in[2];   // [D, F, C] fp32
    const float* bias  = (const float*)d_in[3];   // [D, C]    fp32
    float*       out   = (float*)d_out;           // [B, A, C] fp32

    cudaFuncSetAttribute(gemm_mma_kernel,
                         cudaFuncAttributeMaxDynamicSharedMemorySize, DYN_SMEM);

    mid_kernel<<<MID_BLOCKS, 256>>>(atoms, bonds, W);
    gemm_mma_kernel<<<dim3(MAXTILES, CQ / NT), 256, DYN_SMEM>>>(bias, out);
}